// round 10
// baseline (speedup 1.0000x reference)
#include <cuda_runtime.h>
#include <math.h>
#include <stdint.h>

// ---------------- problem constants ----------------
#define BQ   4
#define LQn  1024
#define CC   256
#define HH   8
#define DFFn 1024
#define LSRC 21760
#define M1   (BQ * LQn)     // 4096 query rows
#define MS   (BQ * LSRC)    // 87040 source rows

typedef unsigned long long u64;

// ---------------- scratch (static device global, no allocs) ----------------
static constexpr size_t OF_QK  = 0;
static constexpr size_t OF_QKP = OF_QK  + (size_t)M1 * CC;      // Q|K packed, 512 cols
static constexpr size_t OF_V   = OF_QKP + (size_t)M1 * 512;
static constexpr size_t OF_ATT = OF_V   + (size_t)M1 * CC;
static constexpr size_t OF_TGA = OF_ATT + (size_t)M1 * CC;
static constexpr size_t OF_Q2  = OF_TGA + (size_t)M1 * CC;
static constexpr size_t OF_VAL = OF_Q2  + (size_t)M1 * CC;
static constexpr size_t OF_OFW = OF_VAL + (size_t)MS * CC;      // off|aw combined out, stride 384
static constexpr size_t OF_DFO = OF_OFW + (size_t)M1 * 384;
static constexpr size_t OF_TMP = OF_DFO + (size_t)M1 * CC;
static constexpr size_t OF_TGB = OF_TMP + (size_t)M1 * CC;
static constexpr size_t OF_FFH = OF_TGB + (size_t)M1 * CC;
static constexpr size_t OF_WCT = OF_FFH + (size_t)M1 * DFFn;    // concat off_w|aw_w [384,256]
static constexpr size_t OF_BCT = OF_WCT + (size_t)384 * CC;     // concat bias [384]
static constexpr size_t SCRATCH_TOTAL = OF_BCT + 384;

__device__ __align__(16) float g_scratch[SCRATCH_TOTAL];

// ---------------- small helpers ----------------
__device__ __forceinline__ unsigned cvt_tf32(float x) {
    unsigned r;
    asm("cvt.rna.tf32.f32 %0, %1;" : "=r"(r) : "f"(x));
    return r;
}
__device__ __forceinline__ u64 f2fma(u64 a, u64 b, u64 c) {
    u64 d;
    asm("fma.rn.f32x2 %0, %1, %2, %3;" : "=l"(d) : "l"(a), "l"(b), "l"(c));
    return d;
}
__device__ __forceinline__ u64 f2mul(u64 a, u64 b) {
    u64 d;
    asm("mul.rn.f32x2 %0, %1, %2;" : "=l"(d) : "l"(a), "l"(b));
    return d;
}
__device__ __forceinline__ u64 f2pack(float lo, float hi) {
    u64 d;
    asm("mov.b64 %0, {%1, %2};" : "=l"(d) : "f"(lo), "f"(hi));
    return d;
}
__device__ __forceinline__ float2 f2unpack(u64 v) {
    float2 r;
    asm("mov.b64 {%0, %1}, %2;" : "=f"(r.x), "=f"(r.y) : "l"(v));
    return r;
}
__device__ __forceinline__ void cp_async16(void* s, const void* g) {
    unsigned sa = (unsigned)__cvta_generic_to_shared(s);
    asm volatile("cp.async.ca.shared.global [%0], [%1], 16;" :: "r"(sa), "l"(g));
}

// ---------------- elementwise add (float4) ----------------
__global__ void add_vec_kernel(const float4* __restrict__ a,
                               const float4* __restrict__ b,
                               float4* __restrict__ o, int n4) {
    int i = blockIdx.x * blockDim.x + threadIdx.x;
    if (i < n4) {
        float4 x = a[i], y = b[i];
        o[i] = make_float4(x.x + y.x, x.y + y.y, x.z + y.z, x.w + y.w);
    }
}

// ---------------- tf32 tensor-core GEMM, 128x128 tiles, 3-stage --------------
template <int ACT>
__global__ void __launch_bounds__(256, 2) tf32_gemm_kernel(
    const float* __restrict__ A, const float* __restrict__ W,
    const float* __restrict__ bias, float* __restrict__ C,
    int K, int N) {
    __shared__ __align__(16) float sA[3][128 * 20];
    __shared__ __align__(16) float sB[3][128 * 20];

    const int tid = threadIdx.x;
    const int m0 = blockIdx.y << 7;
    const int n0 = blockIdx.x << 7;
    const int warp = tid >> 5, lane = tid & 31;
    const int wm = warp >> 2, wn = warp & 3;      // 2 x 4 warp grid
    const int grp = lane >> 2, qid = lane & 3;

    float acc[4][4][4];
#pragma unroll
    for (int mi = 0; mi < 4; ++mi)
#pragma unroll
        for (int ni = 0; ni < 4; ++ni)
#pragma unroll
            for (int r = 0; r < 4; ++r) acc[mi][ni][r] = 0.f;

    const int srow = tid >> 2;            // 0..63
    const int scol = (tid & 3) << 2;      // 0,4,8,12

    const float* Abase = A + (size_t)m0 * K;
    const float* Bbase = W + (size_t)n0 * K;

#define LOAD128(t, buf)                                                     \
    do {                                                                    \
        const float* Ab = Abase + (size_t)(t) * 16;                         \
        const float* Bb = Bbase + (size_t)(t) * 16;                         \
        _Pragma("unroll")                                                   \
        for (int i = 0; i < 2; ++i) {                                       \
            int row = i * 64 + srow;                                        \
            cp_async16(&sA[buf][row * 20 + scol], Ab + (size_t)row * K + scol); \
            cp_async16(&sB[buf][row * 20 + scol], Bb + (size_t)row * K + scol); \
        }                                                                   \
    } while (0)

    const int T = K >> 4;
    LOAD128(0, 0);
    asm volatile("cp.async.commit_group;" ::: "memory");
    LOAD128(1, 1);
    asm volatile("cp.async.commit_group;" ::: "memory");

    for (int t = 0; t < T; ++t) {
        asm volatile("cp.async.wait_group 1;" ::: "memory");
        __syncthreads();

        const float* As = sA[t % 3];
        const float* Bs = sB[t % 3];
#pragma unroll
        for (int s = 0; s < 2; ++s) {
            const int k0 = s << 3;
            unsigned a[4][4], b[4][2];
#pragma unroll
            for (int mi = 0; mi < 4; ++mi) {
                const int r = wm * 64 + mi * 16 + grp;
                a[mi][0] = cvt_tf32(As[r * 20 + k0 + qid]);
                a[mi][1] = cvt_tf32(As[(r + 8) * 20 + k0 + qid]);
                a[mi][2] = cvt_tf32(As[r * 20 + k0 + qid + 4]);
                a[mi][3] = cvt_tf32(As[(r + 8) * 20 + k0 + qid + 4]);
            }
#pragma unroll
            for (int ni = 0; ni < 4; ++ni) {
                const int rB = wn * 32 + ni * 8 + grp;
                b[ni][0] = cvt_tf32(Bs[rB * 20 + k0 + qid]);
                b[ni][1] = cvt_tf32(Bs[rB * 20 + k0 + qid + 4]);
            }
#pragma unroll
            for (int mi = 0; mi < 4; ++mi)
#pragma unroll
                for (int ni = 0; ni < 4; ++ni) {
                    asm volatile(
                        "mma.sync.aligned.m16n8k8.row.col.f32.tf32.tf32.f32 "
                        "{%0,%1,%2,%3}, {%4,%5,%6,%7}, {%8,%9}, {%0,%1,%2,%3};"
                        : "+f"(acc[mi][ni][0]), "+f"(acc[mi][ni][1]),
                          "+f"(acc[mi][ni][2]), "+f"(acc[mi][ni][3])
                        : "r"(a[mi][0]), "r"(a[mi][1]), "r"(a[mi][2]),
                          "r"(a[mi][3]), "r"(b[ni][0]), "r"(b[ni][1]));
                }
        }
        const int tn = t + 2;
        if (tn < T) LOAD128(tn, tn % 3);
        asm volatile("cp.async.commit_group;" ::: "memory");
    }
#undef LOAD128

#pragma unroll
    for (int mi = 0; mi < 4; ++mi) {
        const int row = m0 + wm * 64 + mi * 16 + grp;
#pragma unroll
        for (int ni = 0; ni < 4; ++ni) {
            const int col = n0 + wn * 32 + ni * 8 + (qid << 1);
            const float2 bb = *(const float2*)(bias + col);
            float2 v0, v1;
            v0.x = acc[mi][ni][0] + bb.x; v0.y = acc[mi][ni][1] + bb.y;
            v1.x = acc[mi][ni][2] + bb.x; v1.y = acc[mi][ni][3] + bb.y;
            if (ACT) {
                v0.x = fmaxf(v0.x, 0.f); v0.y = fmaxf(v0.y, 0.f);
                v1.x = fmaxf(v1.x, 0.f); v1.y = fmaxf(v1.y, 0.f);
            }
            *(float2*)(C + (size_t)row * N + col) = v0;
            *(float2*)(C + (size_t)(row + 8) * N + col) = v1;
        }
    }
}

// ---------------- tf32 tensor-core GEMM, 64x64 tiles, 4-stage cp.async -------
template <int ACT>
__global__ void __launch_bounds__(128) tf32_gemm64_kernel(
    const float* __restrict__ A, const float* __restrict__ W,
    const float* __restrict__ bias, float* __restrict__ C,
    int K, int N) {
    __shared__ __align__(16) float sA[4][64 * 20];
    __shared__ __align__(16) float sB[4][64 * 20];

    const int tid = threadIdx.x;
    const int m0 = blockIdx.y << 6;
    const int n0 = blockIdx.x << 6;
    const int warp = tid >> 5, lane = tid & 31;
    const int wm = warp >> 1, wn = warp & 1;      // 2 x 2 warp grid
    const int grp = lane >> 2, qid = lane & 3;
    const int srow = tid >> 2;            // 0..31
    const int scol = (tid & 3) << 2;      // 0,4,8,12

    const float* Abase = A + (size_t)m0 * K;
    const float* Bbase = W + (size_t)n0 * K;

    float acc[2][4][4];
#pragma unroll
    for (int mi = 0; mi < 2; ++mi)
#pragma unroll
        for (int ni = 0; ni < 4; ++ni)
#pragma unroll
            for (int r = 0; r < 4; ++r) acc[mi][ni][r] = 0.f;

#define LOAD64(t, buf)                                                       \
    do {                                                                     \
        const float* Ab = Abase + (size_t)(t) * 16;                          \
        const float* Bb = Bbase + (size_t)(t) * 16;                          \
        cp_async16(&sA[buf][srow * 20 + scol], Ab + (size_t)srow * K + scol);\
        cp_async16(&sA[buf][(srow + 32) * 20 + scol],                        \
                   Ab + (size_t)(srow + 32) * K + scol);                     \
        cp_async16(&sB[buf][srow * 20 + scol], Bb + (size_t)srow * K + scol);\
        cp_async16(&sB[buf][(srow + 32) * 20 + scol],                        \
                   Bb + (size_t)(srow + 32) * K + scol);                     \
    } while (0)

    const int T = K >> 4;
    LOAD64(0, 0);
    asm volatile("cp.async.commit_group;" ::: "memory");
    LOAD64(1, 1);
    asm volatile("cp.async.commit_group;" ::: "memory");
    LOAD64(2, 2);
    asm volatile("cp.async.commit_group;" ::: "memory");

    for (int t = 0; t < T; ++t) {
        asm volatile("cp.async.wait_group 2;" ::: "memory");
        __syncthreads();

        const float* As = sA[t & 3];
        const float* Bs = sB[t & 3];
#pragma unroll
        for (int s = 0; s < 2; ++s) {
            const int k0 = s << 3;
            unsigned a[2][4], b[4][2];
#pragma unroll
            for (int mi = 0; mi < 2; ++mi) {
                const int r = wm * 32 + mi * 16 + grp;
                a[mi][0] = cvt_tf32(As[r * 20 + k0 + qid]);
                a[mi][1] = cvt_tf32(As[(r + 8) * 20 + k0 + qid]);
                a[mi][2] = cvt_tf32(As[r * 20 + k0 + qid + 4]);
                a[mi][3] = cvt_tf32(As[(r + 8) * 20 + k0 + qid + 4]);
            }
#pragma unroll
            for (int ni = 0; ni < 4; ++ni) {
                const int rB = wn * 32 + ni * 8 + grp;
                b[ni][0] = cvt_tf32(Bs[rB * 20 + k0 + qid]);
                b[ni][1] = cvt_tf32(Bs[rB * 20 + k0 + qid + 4]);
            }
#pragma unroll
            for (int mi = 0; mi < 2; ++mi)
#pragma unroll
                for (int ni = 0; ni < 4; ++ni) {
                    asm volatile(
                        "mma.sync.aligned.m16n8k8.row.col.f32.tf32.tf32.f32 "
                        "{%0,%1,%2,%3}, {%4,%5,%6,%7}, {%8,%9}, {%0,%1,%2,%3};"
                        : "+f"(acc[mi][ni][0]), "+f"(acc[mi][ni][1]),
                          "+f"(acc[mi][ni][2]), "+f"(acc[mi][ni][3])
                        : "r"(a[mi][0]), "r"(a[mi][1]), "r"(a[mi][2]),
                          "r"(a[mi][3]), "r"(b[ni][0]), "r"(b[ni][1]));
                }
        }
        const int tn = t + 3;
        if (tn < T) LOAD64(tn, tn & 3);
        asm volatile("cp.async.commit_group;" ::: "memory");
    }
#undef LOAD64

#pragma unroll
    for (int mi = 0; mi < 2; ++mi) {
        const int row = m0 + wm * 32 + mi * 16 + grp;
#pragma unroll
        for (int ni = 0; ni < 4; ++ni) {
            const int col = n0 + wn * 32 + ni * 8 + (qid << 1);
            const float2 bb = *(const float2*)(bias + col);
            float2 v0, v1;
            v0.x = acc[mi][ni][0] + bb.x; v0.y = acc[mi][ni][1] + bb.y;
            v1.x = acc[mi][ni][2] + bb.x; v1.y = acc[mi][ni][3] + bb.y;
            if (ACT) {
                v0.x = fmaxf(v0.x, 0.f); v0.y = fmaxf(v0.y, 0.f);
                v1.x = fmaxf(v1.x, 0.f); v1.y = fmaxf(v1.y, 0.f);
            }
            *(float2*)(C + (size_t)row * N + col) = v0;
            *(float2*)(C + (size_t)(row + 8) * N + col) = v1;
        }
    }
}

// ---------------- fused MHA attention (streaming softmax, f32x2) ------------
__global__ void __launch_bounds__(64) mha_attn_kernel(
    const float* __restrict__ QK, const float* __restrict__ V,
    float* __restrict__ O) {
    const int b = blockIdx.z, h = blockIdx.y;
    const int q0 = blockIdx.x << 6;
    const int t = threadIdx.x;

    __shared__ __align__(16) float sK[64][36];
    __shared__ __align__(16) float sV[64][36];

    const float scale = 0.17677669529663687f;  // 1/sqrt(32)
    u64 q2[16], o2[16];
    const float* qrow = QK + (size_t)(b * LQn + q0 + t) * 512 + h * 32;
#pragma unroll
    for (int i = 0; i < 8; ++i) {
        float4 v4 = *(const float4*)(qrow + i * 4);
        q2[2 * i]     = f2pack(v4.x * scale, v4.y * scale);
        q2[2 * i + 1] = f2pack(v4.z * scale, v4.w * scale);
        o2[2 * i] = 0ull; o2[2 * i + 1] = 0ull;
    }
    float m = -1e30f, l = 0.f;

    for (int kt = 0; kt < LQn / 64; ++kt) {
        const int krow = (kt << 6) + t;
        const float* kr = QK + (size_t)(b * LQn + krow) * 512 + 256 + h * 32;
        const float* vr = V + (size_t)(b * LQn + krow) * 256 + h * 32;
#pragma unroll
        for (int d = 0; d < 32; d += 4) {
            *(float4*)&sK[t][d] = *(const float4*)(kr + d);
            *(float4*)&sV[t][d] = *(const float4*)(vr + d);
        }
        __syncthreads();

#pragma unroll 1
        for (int j0 = 0; j0 < 64; j0 += 8) {
            float s[8];
#pragma unroll
            for (int jj = 0; jj < 8; ++jj) {
                const ulonglong2* kp = (const ulonglong2*)&sK[j0 + jj][0];
                u64 a0 = 0ull, a1 = 0ull;
#pragma unroll
                for (int i = 0; i < 8; ++i) {
                    ulonglong2 kk = kp[i];
                    a0 = f2fma(q2[2 * i], kk.x, a0);
                    a1 = f2fma(q2[2 * i + 1], kk.y, a1);
                }
                const float2 p0 = f2unpack(a0), p1 = f2unpack(a1);
                s[jj] = (p0.x + p0.y) + (p1.x + p1.y);
            }
            float mx = m;
#pragma unroll
            for (int jj = 0; jj < 8; ++jj) mx = fmaxf(mx, s[jj]);
            const float corr = __expf(m - mx);
            m = mx;
            l *= corr;
            const u64 c2 = f2pack(corr, corr);
#pragma unroll
            for (int i = 0; i < 16; ++i) o2[i] = f2mul(o2[i], c2);
#pragma unroll
            for (int jj = 0; jj < 8; ++jj) {
                const float e = __expf(s[jj] - m);
                l += e;
                const u64 e2 = f2pack(e, e);
                const ulonglong2* vp = (const ulonglong2*)&sV[j0 + jj][0];
#pragma unroll
                for (int i = 0; i < 8; ++i) {
                    ulonglong2 vv = vp[i];
                    o2[2 * i]     = f2fma(e2, vv.x, o2[2 * i]);
                    o2[2 * i + 1] = f2fma(e2, vv.y, o2[2 * i + 1]);
                }
            }
        }
        __syncthreads();
    }

    const float inv = 1.f / l;
    float* orow = O + (size_t)(b * LQn + q0 + t) * 256 + h * 32;
#pragma unroll
    for (int i = 0; i < 8; ++i) {
        const float2 a = f2unpack(o2[2 * i]);
        const float2 c = f2unpack(o2[2 * i + 1]);
        float4 v4;
        v4.x = a.x * inv; v4.y = a.y * inv; v4.z = c.x * inv; v4.w = c.y * inv;
        *(float4*)(orow + i * 4) = v4;
    }
}

// ---------------- residual add + LayerNorm (+ optional pos-added copy) ------
template <int WPOS>
__global__ void __launch_bounds__(256) add_ln_kernel(
    const float* __restrict__ X, const float* __restrict__ R,
    const float* __restrict__ g, const float* __restrict__ bb,
    float* __restrict__ out,
    const float* __restrict__ pos, float* __restrict__ out2) {
    const int r = blockIdx.x, t = threadIdx.x;
    const float v = X[(size_t)r * CC + t] + R[(size_t)r * CC + t];
    float s = v, s2 = v * v;
#pragma unroll
    for (int off = 16; off; off >>= 1) {
        s  += __shfl_xor_sync(0xffffffffu, s,  off);
        s2 += __shfl_xor_sync(0xffffffffu, s2, off);
    }
    __shared__ float sh[8], sh2[8];
    const int w = t >> 5, ln = t & 31;
    if (ln == 0) { sh[w] = s; sh2[w] = s2; }
    __syncthreads();
    if (t == 0) {
        float a = 0.f, b2 = 0.f;
#pragma unroll
        for (int i = 0; i < 8; ++i) { a += sh[i]; b2 += sh2[i]; }
        const float mean = a * (1.f / 256.f);
        const float var = b2 * (1.f / 256.f) - mean * mean;
        sh[0] = mean;
        sh2[0] = rsqrtf(var + 1e-5f);
    }
    __syncthreads();
    const float mean = sh[0], inv = sh2[0];
    const float y = (v - mean) * inv * g[t] + bb[t];
    out[(size_t)r * CC + t] = y;
    if (WPOS)
        out2[(size_t)r * CC + t] = y + pos[(size_t)r * CC + t];
}

// ---------------- MS deformable sampling (fused off|aw layout, stride 384) ---
__global__ void __launch_bounds__(256) deform_kernel(
    const float* __restrict__ value,   // [B*LSRC, 256]
    const float* __restrict__ offaw,   // [M1, 384]: cols 0..255 off, 256..383 aw
    const float* __restrict__ refp,    // [B, LQ, L, 2]
    float* __restrict__ out) {         // [M1, 256]
    const int wid = blockIdx.x * 8 + (threadIdx.x >> 5);
    const int lane = threadIdx.x & 31;
    const int h = wid & 7;
    const int q = (wid >> 3) & 1023;
    const int b = wid >> 13;

    const float* rowp = offaw + (size_t)(b * LQn + q) * 384;
    const float* ar = rowp + 256 + h * 16;
    const float logit = (lane < 16) ? ar[lane] : -1e30f;
    float mx = logit;
#pragma unroll
    for (int o = 16; o; o >>= 1)
        mx = fmaxf(mx, __shfl_xor_sync(0xffffffffu, mx, o));
    float e = (lane < 16) ? __expf(logit - mx) : 0.f;
    float se = e;
#pragma unroll
    for (int o = 16; o; o >>= 1) se += __shfl_xor_sync(0xffffffffu, se, o);
    const float p = e / se;

    const int   SZ[4] = {128, 64, 32, 16};
    const int   ST[4] = {0, 16384, 20480, 21504};
    const float* offr = rowp + h * 32;
    const float* refr = refp + (size_t)(b * LQn + q) * 8;

    float acc = 0.f;
#pragma unroll
    for (int l = 0; l < 4; ++l) {
        const int Wl = SZ[l];
        const float Wf = (float)Wl;
        const float rx = refr[l * 2 + 0];
        const float ry = refr[l * 2 + 1];
        const float* vb =
            value + ((size_t)b * LSRC + ST[l]) * 256 + h * 32 + lane;
#pragma unroll
        for (int pt = 0; pt < 4; ++pt) {
            const float ox = offr[(l * 4 + pt) * 2 + 0];
            const float oy = offr[(l * 4 + pt) * 2 + 1];
            const float x = (rx + ox / Wf) * Wf - 0.5f;
            const float y = (ry + oy / Wf) * Wf - 0.5f;
            const float x0f = floorf(x), y0f = floorf(y);
            const int x0 = (int)x0f, y0 = (int)y0f;
            const float wx1 = x - x0f, wx0 = 1.f - wx1;
            const float wy1 = y - y0f, wy0 = 1.f - wy1;
            const float aw = __shfl_sync(0xffffffffu, p, l * 4 + pt);

            if ((unsigned)x0 < (unsigned)Wl && (unsigned)y0 < (unsigned)Wl)
                acc = fmaf(aw * (wx0 * wy0),
                           vb[((size_t)y0 * Wl + x0) * 256], acc);
            if ((unsigned)(x0 + 1) < (unsigned)Wl && (unsigned)y0 < (unsigned)Wl)
                acc = fmaf(aw * (wx1 * wy0),
                           vb[((size_t)y0 * Wl + x0 + 1) * 256], acc);
            if ((unsigned)x0 < (unsigned)Wl && (unsigned)(y0 + 1) < (unsigned)Wl)
                acc = fmaf(aw * (wx0 * wy1),
                           vb[((size_t)(y0 + 1) * Wl + x0) * 256], acc);
            if ((unsigned)(x0 + 1) < (unsigned)Wl &&
                (unsigned)(y0 + 1) < (unsigned)Wl)
                acc = fmaf(aw * (wx1 * wy1),
                           vb[((size_t)(y0 + 1) * Wl + x0 + 1) * 256], acc);
        }
    }
    out[(size_t)(b * LQn + q) * 256 + h * 32 + lane] = acc;
}

// ---------------- launch ----------------------------------------------------
extern "C" void kernel_launch(void* const* d_in, const int* in_sizes, int n_in,
                              void* d_out, int out_size) {
    const float* tgt   = (const float*)d_in[0];
    const float* qpos  = (const float*)d_in[1];
    const float* refp  = (const float*)d_in[2];
    const float* src   = (const float*)d_in[3];
    const float* in_w  = (const float*)d_in[4];
    const float* in_b  = (const float*)d_in[5];
    const float* sa_w  = (const float*)d_in[6];
    const float* sa_b  = (const float*)d_in[7];
    const float* off_w = (const float*)d_in[8];
    const float* off_b = (const float*)d_in[9];
    const float* aw_w  = (const float*)d_in[10];
    const float* aw_b  = (const float*)d_in[11];
    const float* val_w = (const float*)d_in[12];
    const float* val_b = (const float*)d_in[13];
    const float* co_w  = (const float*)d_in[14];
    const float* co_b  = (const float*)d_in[15];
    const float* ln1_g = (const float*)d_in[16];
    const float* ln1_b = (const float*)d_in[17];
    const float* ln2_g = (const float*)d_in[18];
    const float* ln2_b = (const float*)d_in[19];
    const float* ln3_g = (const float*)d_in[20];
    const float* ln3_b = (const float*)d_in[21];
    const float* f1_w  = (const float*)d_in[22];
    const float* f1_b  = (const float*)d_in[23];
    const float* f2_w  = (const float*)d_in[24];
    const float* f2_b  = (const float*)d_in[25];
    float* out = (float*)d_out;

    float* s = nullptr;
    cudaGetSymbolAddress((void**)&s, g_scratch);
    float* qk    = s + OF_QK;
    float* qkp   = s + OF_QKP;
    float* vbuf  = s + OF_V;
    float* attn  = s + OF_ATT;
    float* tgta  = s + OF_TGA;
    float* q2    = s + OF_Q2;
    float* value = s + OF_VAL;
    float* offaw = s + OF_OFW;
    float* dfo   = s + OF_DFO;
    float* tmp   = s + OF_TMP;
    float* tgtb  = s + OF_TGB;
    float* ffh   = s + OF_FFH;
    float* wcat  = s + OF_WCT;
    float* bcat  = s + OF_BCT;

    const int n4 = M1 * CC / 4;

    // side stream + events (host objects; created fresh each call, leaked —
    // no device memory involved, and capture-safe)
    cudaStream_t sB;
    cudaStreamCreateWithFlags(&sB, cudaStreamNonBlocking);
    cudaEvent_t evFork, evV, evJoin;
    cudaEventCreateWithFlags(&evFork, cudaEventDisableTiming);
    cudaEventCreateWithFlags(&evV, cudaEventDisableTiming);
    cudaEventCreateWithFlags(&evJoin, cudaEventDisableTiming);

    // ---- fork: stream B does input-only work -------------------------------
    cudaEventRecord(evFork, 0);
    cudaStreamWaitEvent(sB, evFork, 0);

    cudaMemcpyAsync(wcat, off_w, (size_t)256 * CC * sizeof(float),
                    cudaMemcpyDeviceToDevice, sB);
    cudaMemcpyAsync(wcat + 256 * CC, aw_w, (size_t)128 * CC * sizeof(float),
                    cudaMemcpyDeviceToDevice, sB);
    cudaMemcpyAsync(bcat, off_b, 256 * sizeof(float),
                    cudaMemcpyDeviceToDevice, sB);
    cudaMemcpyAsync(bcat + 256, aw_b, 128 * sizeof(float),
                    cudaMemcpyDeviceToDevice, sB);

    // v projection (needed by MHA)
    tf32_gemm64_kernel<0><<<dim3(CC / 64, M1 / 64), 128, 0, sB>>>(
        tgt, in_w + 512 * CC, in_b + 512, vbuf, CC, CC);
    cudaEventRecord(evV, sB);
    // value projection (needed by deform) — the big one, hidden behind SA
    tf32_gemm_kernel<0><<<dim3(CC / 128, MS / 128), 256, 0, sB>>>(
        src, val_w, val_b, value, CC, CC);
    cudaEventRecord(evJoin, sB);

    // ---- main stream: self-attention block ---------------------------------
    add_vec_kernel<<<(n4 + 255) / 256, 256>>>(
        (const float4*)tgt, (const float4*)qpos, (float4*)qk, n4);
    tf32_gemm64_kernel<0><<<dim3(512 / 64, M1 / 64), 128>>>(
        qk, in_w, in_b, qkp, CC, 512);
    cudaStreamWaitEvent(0, evV, 0);
    mha_attn_kernel<<<dim3(LQn / 64, HH, BQ), 64>>>(qkp, vbuf, attn);
    tf32_gemm64_kernel<0><<<dim3(CC / 64, M1 / 64), 128>>>(
        attn, sa_w, sa_b, tmp, CC, CC);
    // fused: tgta = LN(tmp + tgt), q2 = tgta + qpos
    add_ln_kernel<1><<<M1, 256>>>(tmp, tgt, ln2_g, ln2_b, tgta, qpos, q2);

    // ---- join, then deformable cross-attention block -----------------------
    cudaStreamWaitEvent(0, evJoin, 0);
    // fused off|aw projection: N = 384
    tf32_gemm64_kernel<0><<<dim3(384 / 64, M1 / 64), 128>>>(
        q2, wcat, bcat, offaw, CC, 384);
    deform_kernel<<<(BQ * LQn * HH) / 8, 256>>>(value, offaw, refp, dfo);
    tf32_gemm64_kernel<0><<<dim3(CC / 64, M1 / 64), 128>>>(
        dfo, co_w, co_b, tmp, CC, CC);
    add_ln_kernel<0><<<M1, 256>>>(tmp, tgta, ln1_g, ln1_b, tgtb,
                                  nullptr, nullptr);

    // ---- FFN block ---------------------------------------------------------
    tf32_gemm_kernel<1><<<dim3(DFFn / 128, M1 / 128), 256>>>(
        tgtb, f1_w, f1_b, ffh, CC, DFFn);
    tf32_gemm64_kernel<0><<<dim3(CC / 64, M1 / 64), 128>>>(
        ffh, f2_w, f2_b, tmp, DFFn, CC);
    add_ln_kernel<0><<<M1, 256>>>(tmp, tgtb, ln3_g, ln3_b, out,
                                  nullptr, nullptr);
}

// round 11
// speedup vs baseline: 1.3707x; 1.3707x over previous
#include <cuda_runtime.h>
#include <math.h>
#include <stdint.h>

// ---------------- problem constants ----------------
#define BQ   4
#define LQn  1024
#define CC   256
#define HH   8
#define DFFn 1024
#define LSRC 21760
#define M1   (BQ * LQn)     // 4096 query rows
#define MS   (BQ * LSRC)    // 87040 source rows

typedef unsigned long long u64;

// ---------------- scratch (static device global, no allocs) ----------------
static constexpr size_t OF_QK  = 0;
static constexpr size_t OF_QKP = OF_QK  + (size_t)M1 * CC;      // Q|K packed, 512 cols
static constexpr size_t OF_V   = OF_QKP + (size_t)M1 * 512;
static constexpr size_t OF_ATT = OF_V   + (size_t)M1 * CC;
static constexpr size_t OF_TGA = OF_ATT + (size_t)M1 * CC;
static constexpr size_t OF_Q2  = OF_TGA + (size_t)M1 * CC;
static constexpr size_t OF_VAL = OF_Q2  + (size_t)M1 * CC;
static constexpr size_t OF_OFW = OF_VAL + (size_t)MS * CC;      // off|aw combined out, stride 384
static constexpr size_t OF_DFO = OF_OFW + (size_t)M1 * 384;
static constexpr size_t OF_TMP = OF_DFO + (size_t)M1 * CC;
static constexpr size_t OF_TGB = OF_TMP + (size_t)M1 * CC;
static constexpr size_t OF_FFH = OF_TGB + (size_t)M1 * CC;
static constexpr size_t OF_WCT = OF_FFH + (size_t)M1 * DFFn;    // concat off_w|aw_w [384,256]
static constexpr size_t OF_BCT = OF_WCT + (size_t)384 * CC;     // concat bias [384]
static constexpr size_t SCRATCH_TOTAL = OF_BCT + 384;

__device__ __align__(16) float g_scratch[SCRATCH_TOTAL];

// ---------------- small helpers ----------------
__device__ __forceinline__ unsigned cvt_tf32(float x) {
    unsigned r;
    asm("cvt.rna.tf32.f32 %0, %1;" : "=r"(r) : "f"(x));
    return r;
}
__device__ __forceinline__ u64 f2fma(u64 a, u64 b, u64 c) {
    u64 d;
    asm("fma.rn.f32x2 %0, %1, %2, %3;" : "=l"(d) : "l"(a), "l"(b), "l"(c));
    return d;
}
__device__ __forceinline__ u64 f2mul(u64 a, u64 b) {
    u64 d;
    asm("mul.rn.f32x2 %0, %1, %2;" : "=l"(d) : "l"(a), "l"(b));
    return d;
}
__device__ __forceinline__ u64 f2pack(float lo, float hi) {
    u64 d;
    asm("mov.b64 %0, {%1, %2};" : "=l"(d) : "f"(lo), "f"(hi));
    return d;
}
__device__ __forceinline__ float2 f2unpack(u64 v) {
    float2 r;
    asm("mov.b64 {%0, %1}, %2;" : "=f"(r.x), "=f"(r.y) : "l"(v));
    return r;
}
__device__ __forceinline__ void cp_async16(void* s, const void* g) {
    unsigned sa = (unsigned)__cvta_generic_to_shared(s);
    asm volatile("cp.async.ca.shared.global [%0], [%1], 16;" :: "r"(sa), "l"(g));
}

// ---------------- elementwise add (float4) ----------------
__global__ void add_vec_kernel(const float4* __restrict__ a,
                               const float4* __restrict__ b,
                               float4* __restrict__ o, int n4) {
    int i = blockIdx.x * blockDim.x + threadIdx.x;
    if (i < n4) {
        float4 x = a[i], y = b[i];
        o[i] = make_float4(x.x + y.x, x.y + y.y, x.z + y.z, x.w + y.w);
    }
}

// ---------------- tf32 tensor-core GEMM, 128x128 tiles, 3-stage --------------
template <int ACT>
__global__ void __launch_bounds__(256, 2) tf32_gemm_kernel(
    const float* __restrict__ A, const float* __restrict__ W,
    const float* __restrict__ bias, float* __restrict__ C,
    int K, int N) {
    __shared__ __align__(16) float sA[3][128 * 20];
    __shared__ __align__(16) float sB[3][128 * 20];

    const int tid = threadIdx.x;
    const int m0 = blockIdx.y << 7;
    const int n0 = blockIdx.x << 7;
    const int warp = tid >> 5, lane = tid & 31;
    const int wm = warp >> 2, wn = warp & 3;      // 2 x 4 warp grid
    const int grp = lane >> 2, qid = lane & 3;

    float acc[4][4][4];
#pragma unroll
    for (int mi = 0; mi < 4; ++mi)
#pragma unroll
        for (int ni = 0; ni < 4; ++ni)
#pragma unroll
            for (int r = 0; r < 4; ++r) acc[mi][ni][r] = 0.f;

    const int srow = tid >> 2;            // 0..63
    const int scol = (tid & 3) << 2;      // 0,4,8,12

    const float* Abase = A + (size_t)m0 * K;
    const float* Bbase = W + (size_t)n0 * K;

#define LOAD128(t, buf)                                                     \
    do {                                                                    \
        const float* Ab = Abase + (size_t)(t) * 16;                         \
        const float* Bb = Bbase + (size_t)(t) * 16;                         \
        _Pragma("unroll")                                                   \
        for (int i = 0; i < 2; ++i) {                                       \
            int row = i * 64 + srow;                                        \
            cp_async16(&sA[buf][row * 20 + scol], Ab + (size_t)row * K + scol); \
            cp_async16(&sB[buf][row * 20 + scol], Bb + (size_t)row * K + scol); \
        }                                                                   \
    } while (0)

    const int T = K >> 4;
    LOAD128(0, 0);
    asm volatile("cp.async.commit_group;" ::: "memory");
    LOAD128(1, 1);
    asm volatile("cp.async.commit_group;" ::: "memory");

    for (int t = 0; t < T; ++t) {
        asm volatile("cp.async.wait_group 1;" ::: "memory");
        __syncthreads();

        const float* As = sA[t % 3];
        const float* Bs = sB[t % 3];
#pragma unroll
        for (int s = 0; s < 2; ++s) {
            const int k0 = s << 3;
            unsigned a[4][4], b[4][2];
#pragma unroll
            for (int mi = 0; mi < 4; ++mi) {
                const int r = wm * 64 + mi * 16 + grp;
                a[mi][0] = cvt_tf32(As[r * 20 + k0 + qid]);
                a[mi][1] = cvt_tf32(As[(r + 8) * 20 + k0 + qid]);
                a[mi][2] = cvt_tf32(As[r * 20 + k0 + qid + 4]);
                a[mi][3] = cvt_tf32(As[(r + 8) * 20 + k0 + qid + 4]);
            }
#pragma unroll
            for (int ni = 0; ni < 4; ++ni) {
                const int rB = wn * 32 + ni * 8 + grp;
                b[ni][0] = cvt_tf32(Bs[rB * 20 + k0 + qid]);
                b[ni][1] = cvt_tf32(Bs[rB * 20 + k0 + qid + 4]);
            }
#pragma unroll
            for (int mi = 0; mi < 4; ++mi)
#pragma unroll
                for (int ni = 0; ni < 4; ++ni) {
                    asm volatile(
                        "mma.sync.aligned.m16n8k8.row.col.f32.tf32.tf32.f32 "
                        "{%0,%1,%2,%3}, {%4,%5,%6,%7}, {%8,%9}, {%0,%1,%2,%3};"
                        : "+f"(acc[mi][ni][0]), "+f"(acc[mi][ni][1]),
                          "+f"(acc[mi][ni][2]), "+f"(acc[mi][ni][3])
                        : "r"(a[mi][0]), "r"(a[mi][1]), "r"(a[mi][2]),
                          "r"(a[mi][3]), "r"(b[ni][0]), "r"(b[ni][1]));
                }
        }
        const int tn = t + 2;
        if (tn < T) LOAD128(tn, tn % 3);
        asm volatile("cp.async.commit_group;" ::: "memory");
    }
#undef LOAD128

#pragma unroll
    for (int mi = 0; mi < 4; ++mi) {
        const int row = m0 + wm * 64 + mi * 16 + grp;
#pragma unroll
        for (int ni = 0; ni < 4; ++ni) {
            const int col = n0 + wn * 32 + ni * 8 + (qid << 1);
            const float2 bb = *(const float2*)(bias + col);
            float2 v0, v1;
            v0.x = acc[mi][ni][0] + bb.x; v0.y = acc[mi][ni][1] + bb.y;
            v1.x = acc[mi][ni][2] + bb.x; v1.y = acc[mi][ni][3] + bb.y;
            if (ACT) {
                v0.x = fmaxf(v0.x, 0.f); v0.y = fmaxf(v0.y, 0.f);
                v1.x = fmaxf(v1.x, 0.f); v1.y = fmaxf(v1.y, 0.f);
            }
            *(float2*)(C + (size_t)row * N + col) = v0;
            *(float2*)(C + (size_t)(row + 8) * N + col) = v1;
        }
    }
}

// ---------------- tf32 tensor-core GEMM, 64x64 tiles, 4-stage cp.async -------
template <int ACT>
__global__ void __launch_bounds__(128) tf32_gemm64_kernel(
    const float* __restrict__ A, const float* __restrict__ W,
    const float* __restrict__ bias, float* __restrict__ C,
    int K, int N) {
    __shared__ __align__(16) float sA[4][64 * 20];
    __shared__ __align__(16) float sB[4][64 * 20];

    const int tid = threadIdx.x;
    const int m0 = blockIdx.y << 6;
    const int n0 = blockIdx.x << 6;
    const int warp = tid >> 5, lane = tid & 31;
    const int wm = warp >> 1, wn = warp & 1;      // 2 x 2 warp grid
    const int grp = lane >> 2, qid = lane & 3;
    const int srow = tid >> 2;            // 0..31
    const int scol = (tid & 3) << 2;      // 0,4,8,12

    const float* Abase = A + (size_t)m0 * K;
    const float* Bbase = W + (size_t)n0 * K;

    float acc[2][4][4];
#pragma unroll
    for (int mi = 0; mi < 2; ++mi)
#pragma unroll
        for (int ni = 0; ni < 4; ++ni)
#pragma unroll
            for (int r = 0; r < 4; ++r) acc[mi][ni][r] = 0.f;

#define LOAD64(t, buf)                                                       \
    do {                                                                     \
        const float* Ab = Abase + (size_t)(t) * 16;                          \
        const float* Bb = Bbase + (size_t)(t) * 16;                          \
        cp_async16(&sA[buf][srow * 20 + scol], Ab + (size_t)srow * K + scol);\
        cp_async16(&sA[buf][(srow + 32) * 20 + scol],                        \
                   Ab + (size_t)(srow + 32) * K + scol);                     \
        cp_async16(&sB[buf][srow * 20 + scol], Bb + (size_t)srow * K + scol);\
        cp_async16(&sB[buf][(srow + 32) * 20 + scol],                        \
                   Bb + (size_t)(srow + 32) * K + scol);                     \
    } while (0)

    const int T = K >> 4;
    LOAD64(0, 0);
    asm volatile("cp.async.commit_group;" ::: "memory");
    LOAD64(1, 1);
    asm volatile("cp.async.commit_group;" ::: "memory");
    LOAD64(2, 2);
    asm volatile("cp.async.commit_group;" ::: "memory");

    for (int t = 0; t < T; ++t) {
        asm volatile("cp.async.wait_group 2;" ::: "memory");
        __syncthreads();

        const float* As = sA[t & 3];
        const float* Bs = sB[t & 3];
#pragma unroll
        for (int s = 0; s < 2; ++s) {
            const int k0 = s << 3;
            unsigned a[2][4], b[4][2];
#pragma unroll
            for (int mi = 0; mi < 2; ++mi) {
                const int r = wm * 32 + mi * 16 + grp;
                a[mi][0] = cvt_tf32(As[r * 20 + k0 + qid]);
                a[mi][1] = cvt_tf32(As[(r + 8) * 20 + k0 + qid]);
                a[mi][2] = cvt_tf32(As[r * 20 + k0 + qid + 4]);
                a[mi][3] = cvt_tf32(As[(r + 8) * 20 + k0 + qid + 4]);
            }
#pragma unroll
            for (int ni = 0; ni < 4; ++ni) {
                const int rB = wn * 32 + ni * 8 + grp;
                b[ni][0] = cvt_tf32(Bs[rB * 20 + k0 + qid]);
                b[ni][1] = cvt_tf32(Bs[rB * 20 + k0 + qid + 4]);
            }
#pragma unroll
            for (int mi = 0; mi < 2; ++mi)
#pragma unroll
                for (int ni = 0; ni < 4; ++ni) {
                    asm volatile(
                        "mma.sync.aligned.m16n8k8.row.col.f32.tf32.tf32.f32 "
                        "{%0,%1,%2,%3}, {%4,%5,%6,%7}, {%8,%9}, {%0,%1,%2,%3};"
                        : "+f"(acc[mi][ni][0]), "+f"(acc[mi][ni][1]),
                          "+f"(acc[mi][ni][2]), "+f"(acc[mi][ni][3])
                        : "r"(a[mi][0]), "r"(a[mi][1]), "r"(a[mi][2]),
                          "r"(a[mi][3]), "r"(b[ni][0]), "r"(b[ni][1]));
                }
        }
        const int tn = t + 3;
        if (tn < T) LOAD64(tn, tn & 3);
        asm volatile("cp.async.commit_group;" ::: "memory");
    }
#undef LOAD64

#pragma unroll
    for (int mi = 0; mi < 2; ++mi) {
        const int row = m0 + wm * 32 + mi * 16 + grp;
#pragma unroll
        for (int ni = 0; ni < 4; ++ni) {
            const int col = n0 + wn * 32 + ni * 8 + (qid << 1);
            const float2 bb = *(const float2*)(bias + col);
            float2 v0, v1;
            v0.x = acc[mi][ni][0] + bb.x; v0.y = acc[mi][ni][1] + bb.y;
            v1.x = acc[mi][ni][2] + bb.x; v1.y = acc[mi][ni][3] + bb.y;
            if (ACT) {
                v0.x = fmaxf(v0.x, 0.f); v0.y = fmaxf(v0.y, 0.f);
                v1.x = fmaxf(v1.x, 0.f); v1.y = fmaxf(v1.y, 0.f);
            }
            *(float2*)(C + (size_t)row * N + col) = v0;
            *(float2*)(C + (size_t)(row + 8) * N + col) = v1;
        }
    }
}

// ---------------- fused MHA attention, split-K (streaming softmax, f32x2) ---
// 128 threads: tq = t&63 selects query q0+tq; kh = t>>6 selects key half.
// Each half processes 8 tiles of 64 keys with its own sK/sV buffer, then the
// two partials (m, l, o[32]) are merged through shared memory.
__global__ void __launch_bounds__(128) mha_attn_kernel(
    const float* __restrict__ QK, const float* __restrict__ V,
    float* __restrict__ O) {
    const int b = blockIdx.z, h = blockIdx.y;
    const int q0 = blockIdx.x << 6;
    const int tq = threadIdx.x & 63;
    const int kh = threadIdx.x >> 6;   // 0 or 1

    __shared__ __align__(16) float sK[2][64][36];
    __shared__ __align__(16) float sV[2][64][36];

    const float scale = 0.17677669529663687f;  // 1/sqrt(32)
    u64 q2[16], o2[16];
    const float* qrow = QK + (size_t)(b * LQn + q0 + tq) * 512 + h * 32;
#pragma unroll
    for (int i = 0; i < 8; ++i) {
        float4 v4 = *(const float4*)(qrow + i * 4);
        q2[2 * i]     = f2pack(v4.x * scale, v4.y * scale);
        q2[2 * i + 1] = f2pack(v4.z * scale, v4.w * scale);
        o2[2 * i] = 0ull; o2[2 * i + 1] = 0ull;
    }
    float m = -1e30f, l = 0.f;

    const int ktEnd = (kh + 1) * (LQn / 128);
#pragma unroll 1
    for (int kt = kh * (LQn / 128); kt < ktEnd; ++kt) {
        const int krow = (kt << 6) + tq;
        const float* kr = QK + (size_t)(b * LQn + krow) * 512 + 256 + h * 32;
        const float* vr = V + (size_t)(b * LQn + krow) * 256 + h * 32;
#pragma unroll
        for (int d = 0; d < 32; d += 4) {
            *(float4*)&sK[kh][tq][d] = *(const float4*)(kr + d);
            *(float4*)&sV[kh][tq][d] = *(const float4*)(vr + d);
        }
        __syncthreads();

#pragma unroll 1
        for (int j0 = 0; j0 < 64; j0 += 8) {
            float s[8];
#pragma unroll
            for (int jj = 0; jj < 8; ++jj) {
                const ulonglong2* kp = (const ulonglong2*)&sK[kh][j0 + jj][0];
                u64 a0 = 0ull, a1 = 0ull;
#pragma unroll
                for (int i = 0; i < 8; ++i) {
                    ulonglong2 kk = kp[i];
                    a0 = f2fma(q2[2 * i], kk.x, a0);
                    a1 = f2fma(q2[2 * i + 1], kk.y, a1);
                }
                const float2 p0 = f2unpack(a0), p1 = f2unpack(a1);
                s[jj] = (p0.x + p0.y) + (p1.x + p1.y);
            }
            float mx = m;
#pragma unroll
            for (int jj = 0; jj < 8; ++jj) mx = fmaxf(mx, s[jj]);
            const float corr = __expf(m - mx);
            m = mx;
            l *= corr;
            const u64 c2 = f2pack(corr, corr);
#pragma unroll
            for (int i = 0; i < 16; ++i) o2[i] = f2mul(o2[i], c2);
#pragma unroll
            for (int jj = 0; jj < 8; ++jj) {
                const float e = __expf(s[jj] - m);
                l += e;
                const u64 e2 = f2pack(e, e);
                const ulonglong2* vp = (const ulonglong2*)&sV[kh][j0 + jj][0];
#pragma unroll
                for (int i = 0; i < 8; ++i) {
                    ulonglong2 vv = vp[i];
                    o2[2 * i]     = f2fma(e2, vv.x, o2[2 * i]);
                    o2[2 * i + 1] = f2fma(e2, vv.y, o2[2 * i + 1]);
                }
            }
        }
        __syncthreads();
    }

    // ---- merge the two key-half partials ----
    if (kh == 1) {
        sK[0][tq][0] = m;
        sK[0][tq][1] = l;
#pragma unroll
        for (int i = 0; i < 16; ++i)
            *(u64*)&sV[1][tq][2 * i] = o2[i];
    }
    __syncthreads();
    if (kh == 0) {
        const float m1 = sK[0][tq][0];
        const float l1 = sK[0][tq][1];
        const float M = fmaxf(m, m1);
        const float c0 = __expf(m - M);
        const float c1 = __expf(m1 - M);
        const float L = l * c0 + l1 * c1;
        const float inv = 1.f / L;
        const u64 c02 = f2pack(c0 * inv, c0 * inv);
        const u64 c12 = f2pack(c1 * inv, c1 * inv);
        float* orow = O + (size_t)(b * LQn + q0 + tq) * 256 + h * 32;
#pragma unroll
        for (int i = 0; i < 8; ++i) {
            u64 r0 = f2mul(o2[2 * i], c02);
            u64 r1 = f2mul(o2[2 * i + 1], c02);
            r0 = f2fma(*(const u64*)&sV[1][tq][4 * i], c12, r0);
            r1 = f2fma(*(const u64*)&sV[1][tq][4 * i + 2], c12, r1);
            const float2 a = f2unpack(r0);
            const float2 c = f2unpack(r1);
            float4 v4;
            v4.x = a.x; v4.y = a.y; v4.z = c.x; v4.w = c.y;
            *(float4*)(orow + i * 4) = v4;
        }
    }
}

// ---------------- residual add + LayerNorm (+ optional pos-added copy) ------
template <int WPOS>
__global__ void __launch_bounds__(256) add_ln_kernel(
    const float* __restrict__ X, const float* __restrict__ R,
    const float* __restrict__ g, const float* __restrict__ bb,
    float* __restrict__ out,
    const float* __restrict__ pos, float* __restrict__ out2) {
    const int r = blockIdx.x, t = threadIdx.x;
    const float v = X[(size_t)r * CC + t] + R[(size_t)r * CC + t];
    float s = v, s2 = v * v;
#pragma unroll
    for (int off = 16; off; off >>= 1) {
        s  += __shfl_xor_sync(0xffffffffu, s,  off);
        s2 += __shfl_xor_sync(0xffffffffu, s2, off);
    }
    __shared__ float sh[8], sh2[8];
    const int w = t >> 5, ln = t & 31;
    if (ln == 0) { sh[w] = s; sh2[w] = s2; }
    __syncthreads();
    if (t == 0) {
        float a = 0.f, b2 = 0.f;
#pragma unroll
        for (int i = 0; i < 8; ++i) { a += sh[i]; b2 += sh2[i]; }
        const float mean = a * (1.f / 256.f);
        const float var = b2 * (1.f / 256.f) - mean * mean;
        sh[0] = mean;
        sh2[0] = rsqrtf(var + 1e-5f);
    }
    __syncthreads();
    const float mean = sh[0], inv = sh2[0];
    const float y = (v - mean) * inv * g[t] + bb[t];
    out[(size_t)r * CC + t] = y;
    if (WPOS)
        out2[(size_t)r * CC + t] = y + pos[(size_t)r * CC + t];
}

// ---------------- MS deformable sampling (fused off|aw layout, stride 384) ---
__global__ void __launch_bounds__(256) deform_kernel(
    const float* __restrict__ value,   // [B*LSRC, 256]
    const float* __restrict__ offaw,   // [M1, 384]: cols 0..255 off, 256..383 aw
    const float* __restrict__ refp,    // [B, LQ, L, 2]
    float* __restrict__ out) {         // [M1, 256]
    const int wid = blockIdx.x * 8 + (threadIdx.x >> 5);
    const int lane = threadIdx.x & 31;
    const int h = wid & 7;
    const int q = (wid >> 3) & 1023;
    const int b = wid >> 13;

    const float* rowp = offaw + (size_t)(b * LQn + q) * 384;
    const float* ar = rowp + 256 + h * 16;
    const float logit = (lane < 16) ? ar[lane] : -1e30f;
    float mx = logit;
#pragma unroll
    for (int o = 16; o; o >>= 1)
        mx = fmaxf(mx, __shfl_xor_sync(0xffffffffu, mx, o));
    float e = (lane < 16) ? __expf(logit - mx) : 0.f;
    float se = e;
#pragma unroll
    for (int o = 16; o; o >>= 1) se += __shfl_xor_sync(0xffffffffu, se, o);
    const float p = e / se;

    const int   SZ[4] = {128, 64, 32, 16};
    const int   ST[4] = {0, 16384, 20480, 21504};
    const float* offr = rowp + h * 32;
    const float* refr = refp + (size_t)(b * LQn + q) * 8;

    float acc = 0.f;
#pragma unroll
    for (int l = 0; l < 4; ++l) {
        const int Wl = SZ[l];
        const float Wf = (float)Wl;
        const float rx = refr[l * 2 + 0];
        const float ry = refr[l * 2 + 1];
        const float* vb =
            value + ((size_t)b * LSRC + ST[l]) * 256 + h * 32 + lane;
#pragma unroll
        for (int pt = 0; pt < 4; ++pt) {
            const float ox = offr[(l * 4 + pt) * 2 + 0];
            const float oy = offr[(l * 4 + pt) * 2 + 1];
            const float x = (rx + ox / Wf) * Wf - 0.5f;
            const float y = (ry + oy / Wf) * Wf - 0.5f;
            const float x0f = floorf(x), y0f = floorf(y);
            const int x0 = (int)x0f, y0 = (int)y0f;
            const float wx1 = x - x0f, wx0 = 1.f - wx1;
            const float wy1 = y - y0f, wy0 = 1.f - wy1;
            const float aw = __shfl_sync(0xffffffffu, p, l * 4 + pt);

            if ((unsigned)x0 < (unsigned)Wl && (unsigned)y0 < (unsigned)Wl)
                acc = fmaf(aw * (wx0 * wy0),
                           vb[((size_t)y0 * Wl + x0) * 256], acc);
            if ((unsigned)(x0 + 1) < (unsigned)Wl && (unsigned)y0 < (unsigned)Wl)
                acc = fmaf(aw * (wx1 * wy0),
                           vb[((size_t)y0 * Wl + x0 + 1) * 256], acc);
            if ((unsigned)x0 < (unsigned)Wl && (unsigned)(y0 + 1) < (unsigned)Wl)
                acc = fmaf(aw * (wx0 * wy1),
                           vb[((size_t)(y0 + 1) * Wl + x0) * 256], acc);
            if ((unsigned)(x0 + 1) < (unsigned)Wl &&
                (unsigned)(y0 + 1) < (unsigned)Wl)
                acc = fmaf(aw * (wx1 * wy1),
                           vb[((size_t)(y0 + 1) * Wl + x0 + 1) * 256], acc);
        }
    }
    out[(size_t)(b * LQn + q) * 256 + h * 32 + lane] = acc;
}

// ---------------- launch (serial, single stream) -----------------------------
extern "C" void kernel_launch(void* const* d_in, const int* in_sizes, int n_in,
                              void* d_out, int out_size) {
    const float* tgt   = (const float*)d_in[0];
    const float* qpos  = (const float*)d_in[1];
    const float* refp  = (const float*)d_in[2];
    const float* src   = (const float*)d_in[3];
    const float* in_w  = (const float*)d_in[4];
    const float* in_b  = (const float*)d_in[5];
    const float* sa_w  = (const float*)d_in[6];
    const float* sa_b  = (const float*)d_in[7];
    const float* off_w = (const float*)d_in[8];
    const float* off_b = (const float*)d_in[9];
    const float* aw_w  = (const float*)d_in[10];
    const float* aw_b  = (const float*)d_in[11];
    const float* val_w = (const float*)d_in[12];
    const float* val_b = (const float*)d_in[13];
    const float* co_w  = (const float*)d_in[14];
    const float* co_b  = (const float*)d_in[15];
    const float* ln1_g = (const float*)d_in[16];
    const float* ln1_b = (const float*)d_in[17];
    const float* ln2_g = (const float*)d_in[18];
    const float* ln2_b = (const float*)d_in[19];
    const float* ln3_g = (const float*)d_in[20];
    const float* ln3_b = (const float*)d_in[21];
    const float* f1_w  = (const float*)d_in[22];
    const float* f1_b  = (const float*)d_in[23];
    const float* f2_w  = (const float*)d_in[24];
    const float* f2_b  = (const float*)d_in[25];
    float* out = (float*)d_out;

    float* s = nullptr;
    cudaGetSymbolAddress((void**)&s, g_scratch);
    float* qk    = s + OF_QK;
    float* qkp   = s + OF_QKP;
    float* vbuf  = s + OF_V;
    float* attn  = s + OF_ATT;
    float* tgta  = s + OF_TGA;
    float* q2    = s + OF_Q2;
    float* value = s + OF_VAL;
    float* offaw = s + OF_OFW;
    float* dfo   = s + OF_DFO;
    float* tmp   = s + OF_TMP;
    float* tgtb  = s + OF_TGB;
    float* ffh   = s + OF_FFH;
    float* wcat  = s + OF_WCT;
    float* bcat  = s + OF_BCT;

    const int n4 = M1 * CC / 4;

    // concat off|aw weights (D2D, captured as memcpy nodes, ~0.4 MB total)
    cudaMemcpyAsync(wcat, off_w, (size_t)256 * CC * sizeof(float),
                    cudaMemcpyDeviceToDevice, 0);
    cudaMemcpyAsync(wcat + 256 * CC, aw_w, (size_t)128 * CC * sizeof(float),
                    cudaMemcpyDeviceToDevice, 0);
    cudaMemcpyAsync(bcat, off_b, 256 * sizeof(float),
                    cudaMemcpyDeviceToDevice, 0);
    cudaMemcpyAsync(bcat + 256, aw_b, 128 * sizeof(float),
                    cudaMemcpyDeviceToDevice, 0);

    // value projection (independent; large grid -> 128-tile kernel)
    tf32_gemm_kernel<0><<<dim3(CC / 128, MS / 128), 256>>>(
        src, val_w, val_b, value, CC, CC);

    // --- self-attention block ---
    add_vec_kernel<<<(n4 + 255) / 256, 256>>>(
        (const float4*)tgt, (const float4*)qpos, (float4*)qk, n4);
    tf32_gemm64_kernel<0><<<dim3(512 / 64, M1 / 64), 128>>>(
        qk, in_w, in_b, qkp, CC, 512);
    tf32_gemm64_kernel<0><<<dim3(CC / 64, M1 / 64), 128>>>(
        tgt, in_w + 512 * CC, in_b + 512, vbuf, CC, CC);
    mha_attn_kernel<<<dim3(LQn / 64, HH, BQ), 128>>>(qkp, vbuf, attn);
    tf32_gemm64_kernel<0><<<dim3(CC / 64, M1 / 64), 128>>>(
        attn, sa_w, sa_b, tmp, CC, CC);
    // fused: tgta = LN(tmp + tgt), q2 = tgta + qpos
    add_ln_kernel<1><<<M1, 256>>>(tmp, tgt, ln2_g, ln2_b, tgta, qpos, q2);

    // --- deformable cross-attention block ---
    tf32_gemm64_kernel<0><<<dim3(384 / 64, M1 / 64), 128>>>(
        q2, wcat, bcat, offaw, CC, 384);
    deform_kernel<<<(BQ * LQn * HH) / 8, 256>>>(value, offaw, refp, dfo);
    tf32_gemm64_kernel<0><<<dim3(CC / 64, M1 / 64), 128>>>(
        dfo, co_w, co_b, tmp, CC, CC);
    add_ln_kernel<0><<<M1, 256>>>(tmp, tgta, ln1_g, ln1_b, tgtb,
                                  nullptr, nullptr);

    // --- FFN block ---
    tf32_gemm_kernel<1><<<dim3(DFFn / 128, M1 / 128), 256>>>(
        tgtb, f1_w, f1_b, ffh, CC, DFFn);
    tf32_gemm64_kernel<0><<<dim3(CC / 64, M1 / 64), 128>>>(
        ffh, f2_w, f2_b, tmp, DFFn, CC);
    add_ln_kernel<0><<<M1, 256>>>(tmp, tgtb, ln3_g, ln3_b, out,
                                  nullptr, nullptr);
}